// round 15
// baseline (speedup 1.0000x reference)
#include <cuda_runtime.h>
#include <math.h>
#include <stdint.h>

// Problem constants (hardcoded from setup_inputs)
#define NB 2
#define LS 1024
#define DS 1024
#define NHD 16
#define HDM 64
#define NLR (NB*LS)   // 2048

// ---------------- scratch (__device__ globals; no allocation allowed) -------
__device__ float g_q [NLR*DS];          // 8 MB  : X@Wq, tf32-rounded
__device__ float g_k [NLR*DS];          // 8 MB  : Y@We, tf32-rounded
__device__ float g_vT[NLR*DS];          // 8 MB  : Y@Wv, [n][h][x][c], tf32-rounded
__device__ float g_R [LS*DS];           // 4 MB  : matrix_r rows 0..L-1, tf32-rounded
__device__ float g_Qm[LS*DS];           // 4 MB  : R[0:L]@Wr, tf32-rounded
__device__ float g_WT[4*DS*DS];         // 16 MB : Wq/We/Wv/Wr transposed+rounded [n][k]
__device__ float g_Xr[NLR*DS];          // 8 MB  : X tf32-rounded
__device__ float g_Yr[NLR*DS];          // 8 MB  : Y tf32-rounded
__device__ float g_WoR[DS*DS];          // 4 MB  : Wo tf32-rounded
__device__ float g_ck[NB*NHD*LS];       // cb_h . k_c
__device__ float g_Dv[NHD*LS];          // pb_h . Qm_r
__device__ float g_O [NLR*DS];          // attention output, tf32-rounded
__device__ float g_Z [NLR*DS];          // pre-layernorm

// ---------------- helpers ----------------------------------------------------
__device__ __forceinline__ uint32_t f2tf(float f) {
    uint32_t u; asm("cvt.rna.tf32.f32 %0, %1;" : "=r"(u) : "f"(f)); return u;
}
__device__ __forceinline__ float rndtf(float f) { return __uint_as_float(f2tf(f)); }
__device__ __forceinline__ int swz3(int r) { return (r ^ (r >> 2)) & 7; }
__device__ __forceinline__ uint32_t smem_u32(const void* p) {
    return (uint32_t)__cvta_generic_to_shared(p);
}
__device__ __forceinline__ void cp16(uint32_t saddr, const void* g) {
    asm volatile("cp.async.cg.shared.global [%0], [%1], 16;" :: "r"(saddr), "l"(g));
}

// ============================================================================
// merged prep kernel: blocks [0,2048) rope | [2048,6144) weight-T | rest rnd
// ============================================================================
__global__ void k_prep(const float* __restrict__ X, const float* __restrict__ Y,
                       const float* __restrict__ W0, const float* __restrict__ W1,
                       const float* __restrict__ W2, const float* __restrict__ W3,
                       const float* __restrict__ Wo) {
    int b = blockIdx.x;
    if (b < 2048) {
        int idx = b * 256 + threadIdx.x;
        int r = idx / (DS/2), j = idx % (DS/2);
        float ex   = -(float)(2 * j) * (13.287712379549449f / (float)DS);
        float invf = exp2f(ex);
        float ang  = (float)(r - (LS - 1)) * invf;
        float s, c;
        sincosf(ang, &s, &c);
        g_R[r*DS + 2*j]   = rndtf(s);
        g_R[r*DS + 2*j+1] = rndtf(c);
    } else if (b < 6144) {
        __shared__ float t[32][33];
        int b2 = b - 2048;
        int z = b2 >> 10, rem = b2 & 1023;
        int bx = (rem & 31) * 32, by = (rem >> 5) * 32;
        const float* src = (z == 0) ? W0 : (z == 1) ? W1 : (z == 2) ? W2 : W3;
        float* dst = g_WT + (size_t)z * DS * DS;
        int tx = threadIdx.x & 31, ty4 = (threadIdx.x >> 5) * 4;
#pragma unroll
        for (int i = 0; i < 4; i++)
            t[ty4 + i][tx] = src[(size_t)(by + ty4 + i) * DS + bx + tx];
        __syncthreads();
#pragma unroll
        for (int i = 0; i < 4; i++)
            dst[(size_t)(bx + ty4 + i) * DS + by + tx] = rndtf(t[tx][ty4 + i]);
    } else {
        int idx = (b - 6144) * 256 + threadIdx.x;
        const int NX = NLR * DS / 4;
        const int NW = DS * DS / 4;
        const float4* src; float* dst; int off;
        if (idx < NX)            { src = (const float4*)X;  dst = g_Xr;  off = idx; }
        else if (idx < 2 * NX)   { src = (const float4*)Y;  dst = g_Yr;  off = idx - NX; }
        else if (idx < 2*NX+NW)  { src = (const float4*)Wo; dst = g_WoR; off = idx - 2*NX; }
        else return;
        float4 v = src[off];
        v.x = rndtf(v.x); v.y = rndtf(v.y); v.z = rndtf(v.z); v.w = rndtf(v.w);
        *(float4*)&dst[(size_t)off * 4] = v;
    }
}

// ---------------- MMA / ldmatrix ----------------------------------------------
__device__ __forceinline__ void mma_tf32(float c[4],
    uint32_t a0, uint32_t a1, uint32_t a2, uint32_t a3,
    uint32_t b0, uint32_t b1)
{
    asm volatile(
        "mma.sync.aligned.m16n8k8.row.col.f32.tf32.tf32.f32 "
        "{%0,%1,%2,%3}, {%4,%5,%6,%7}, {%8,%9}, {%0,%1,%2,%3};"
        : "+f"(c[0]), "+f"(c[1]), "+f"(c[2]), "+f"(c[3])
        : "r"(a0), "r"(a1), "r"(a2), "r"(a3), "r"(b0), "r"(b1));
}

template<int PG>
__device__ __forceinline__ void ldsmA(uint32_t fr[4], uint32_t base, int mb, int kg, int lane) {
    int t = lane >> 3, tr = lane & 7;
    int row = mb + ((t & 1) << 3) + tr;
    int cg  = (kg + (t >> 1)) ^ swz3(row);
    uint32_t a = base + (uint32_t)((row * PG + cg) << 4);
    asm volatile("ldmatrix.sync.aligned.m8n8.x4.shared.b16 {%0,%1,%2,%3}, [%4];"
        : "=r"(fr[0]), "=r"(fr[1]), "=r"(fr[2]), "=r"(fr[3]) : "r"(a));
}
template<int PG>
__device__ __forceinline__ void ldsmB(uint32_t fr[4], uint32_t base, int nb, int kg, int lane) {
    int t = lane >> 3, tr = lane & 7;
    int row = nb + ((t >> 1) << 3) + tr;
    int cg  = (kg + (t & 1)) ^ swz3(row);
    uint32_t a = base + (uint32_t)((row * PG + cg) << 4);
    asm volatile("ldmatrix.sync.aligned.m8n8.x4.shared.b16 {%0,%1,%2,%3}, [%4];"
        : "=r"(fr[0]), "=r"(fr[1]), "=r"(fr[2]), "=r"(fr[3]) : "r"(a));
}

// ============================================================================
// TF32 GEMM v3 (unchanged): CTA 128x128, BK=32, 3-stage cp.async
// ============================================================================
#define GEMM_STAGES 3
#define GEMM_SMEM_BYTES (GEMM_STAGES * 32768)

template<int EPIM>
__device__ __forceinline__ void mma_gemm_body(
    const float* __restrict__ A, int lda,
    const float* __restrict__ B, int ldb,
    float* __restrict__ C, int ldc, int K,
    int m0, int n0,
    const float* __restrict__ bias, const float* __restrict__ res,
    uint32_t* smem)
{
    int tid  = threadIdx.x;
    int warp = tid >> 5, lane = tid & 31;
    int wm = warp >> 1, wn = warp & 1;
    int g = lane >> 2, tg = lane & 3;
    uint32_t base = smem_u32(smem);
    int nch = K >> 5;

    float acc[2][8][4];
#pragma unroll
    for (int mt = 0; mt < 2; mt++)
#pragma unroll
        for (int nt = 0; nt < 8; nt++)
#pragma unroll
            for (int c = 0; c < 4; c++) acc[mt][nt][c] = 0.f;

    auto fill = [&](int kc, int st) {
        uint32_t bA = base + (uint32_t)st * 32768, bB = bA + 16384;
        int kk = kc * 32;
#pragma unroll
        for (int it = 0; it < 4; it++) {
            int f = tid + it * 256, row = f >> 3, c4 = f & 7;
            uint32_t so = (uint32_t)((row * 8 + (c4 ^ swz3(row))) << 4);
            cp16(bA + so, &A[(size_t)(m0 + row) * lda + kk + c4 * 4]);
            cp16(bB + so, &B[(size_t)(n0 + row) * ldb + kk + c4 * 4]);
        }
        asm volatile("cp.async.commit_group;" ::: "memory");
    };

    fill(0, 0);
    if (nch > 1) fill(1, 1);

    for (int j = 0; j < nch; j++) {
        if (j + 1 < nch) asm volatile("cp.async.wait_group 1;" ::: "memory");
        else             asm volatile("cp.async.wait_group 0;" ::: "memory");
        __syncthreads();
        if (j + 2 < nch) fill(j + 2, (j + 2) % GEMM_STAGES);
        uint32_t bA = base + (uint32_t)(j % GEMM_STAGES) * 32768;
        uint32_t bB = bA + 16384;
#pragma unroll
        for (int kg = 0; kg < 8; kg += 2) {
            uint32_t af[2][4], bf[4][4];
            ldsmA<8>(af[0], bA, wm * 32,      kg, lane);
            ldsmA<8>(af[1], bA, wm * 32 + 16, kg, lane);
#pragma unroll
            for (int p = 0; p < 4; p++)
                ldsmB<8>(bf[p], bB, wn * 64 + p * 16, kg, lane);
#pragma unroll
            for (int mt = 0; mt < 2; mt++)
#pragma unroll
                for (int p = 0; p < 4; p++) {
                    mma_tf32(acc[mt][2*p],   af[mt][0], af[mt][1], af[mt][2], af[mt][3],
                             bf[p][0], bf[p][1]);
                    mma_tf32(acc[mt][2*p+1], af[mt][0], af[mt][1], af[mt][2], af[mt][3],
                             bf[p][2], bf[p][3]);
                }
        }
    }

#pragma unroll
    for (int mt = 0; mt < 2; mt++) {
        int row = m0 + wm * 32 + mt * 16 + g;
#pragma unroll
        for (int nt = 0; nt < 8; nt++) {
            int col = n0 + wn * 64 + nt * 8 + tg * 2;
            if (EPIM == 2) {
                int n_ = row >> 10, c_ = row & 1023;
                size_t b0 = ((size_t)n_ * (NHD * HDM) + col) * LS + c_;
                g_vT[b0]          = rndtf(acc[mt][nt][0]);
                g_vT[b0 + LS]     = rndtf(acc[mt][nt][1]);
                g_vT[b0 + 8]      = rndtf(acc[mt][nt][2]);
                g_vT[b0 + LS + 8] = rndtf(acc[mt][nt][3]);
            } else {
                float2 v0, v1;
                if (EPIM == 1) {
                    v0.x = acc[mt][nt][0] + bias[col]     + res[(size_t)row * ldc + col];
                    v0.y = acc[mt][nt][1] + bias[col + 1] + res[(size_t)row * ldc + col + 1];
                    v1.x = acc[mt][nt][2] + bias[col]     + res[(size_t)(row + 8) * ldc + col];
                    v1.y = acc[mt][nt][3] + bias[col + 1] + res[(size_t)(row + 8) * ldc + col + 1];
                } else {
                    v0.x = rndtf(acc[mt][nt][0]); v0.y = rndtf(acc[mt][nt][1]);
                    v1.x = rndtf(acc[mt][nt][2]); v1.y = rndtf(acc[mt][nt][3]);
                }
                *(float2*)&C[(size_t)row * ldc + col]       = v0;
                *(float2*)&C[(size_t)(row + 8) * ldc + col] = v1;
            }
        }
    }
}

template<int EPIM>
__global__ void __launch_bounds__(256, 2) k_mma(
    const float* __restrict__ A, int lda,
    const float* __restrict__ B, int ldb,
    float* __restrict__ C, int ldc, int K,
    const float* __restrict__ bias, const float* __restrict__ res)
{
    extern __shared__ uint32_t smemu[];
    mma_gemm_body<EPIM>(A, lda, B, ldb, C, ldc, K,
                        blockIdx.y * 128, blockIdx.x * 128, bias, res, smemu);
}

__global__ void __launch_bounds__(256, 2) k_mma_proj()
{
    extern __shared__ uint32_t smemu[];
    int z = blockIdx.z;
    if (z == 3 && blockIdx.y >= LS / 128) return;
    const float* A = (z == 0) ? g_Xr : (z == 3) ? g_R : g_Yr;
    const float* B = g_WT + (size_t)z * DS * DS;
    if (z == 2) {
        mma_gemm_body<2>(A, DS, B, DS, nullptr, DS, DS,
                         blockIdx.y * 128, blockIdx.x * 128, nullptr, nullptr, smemu);
    } else {
        float* C = (z == 0) ? g_q : (z == 1) ? g_k : g_Qm;
        mma_gemm_body<0>(A, DS, B, DS, C, DS, DS,
                         blockIdx.y * 128, blockIdx.x * 128, nullptr, nullptr, smemu);
    }
}

// ---------------- small dot-product tables ----------------------------------
__global__ void k_tabs(const float* __restrict__ cb, const float* __restrict__ pb) {
    int l16  = threadIdx.x & 15;
    int wrow = (int)blockIdx.x * 16 + (threadIdx.x >> 4);
    float4 w, k;
    if (blockIdx.x < (NB * NHD * LS / 16)) {
        int n = wrow >> 14, h = (wrow >> 10) & 15, c = wrow & 1023;
        w = *(const float4*)&cb[h * HDM + l16 * 4];
        k = *(const float4*)&g_k[(size_t)(n * LS + c) * DS + h * HDM + l16 * 4];
        float s = w.x*k.x + w.y*k.y + w.z*k.z + w.w*k.w;
        s += __shfl_xor_sync(0xffffffffu, s, 8);
        s += __shfl_xor_sync(0xffffffffu, s, 4);
        s += __shfl_xor_sync(0xffffffffu, s, 2);
        s += __shfl_xor_sync(0xffffffffu, s, 1);
        if (l16 == 0) g_ck[wrow] = s;
    } else {
        int row = wrow - NB * NHD * LS;
        int h = row >> 10, r = row & 1023;
        w = *(const float4*)&pb[h * HDM + l16 * 4];
        k = *(const float4*)&g_Qm[(size_t)r * DS + h * HDM + l16 * 4];
        float s = w.x*k.x + w.y*k.y + w.z*k.z + w.w*k.w;
        s += __shfl_xor_sync(0xffffffffu, s, 8);
        s += __shfl_xor_sync(0xffffffffu, s, 4);
        s += __shfl_xor_sync(0xffffffffu, s, 2);
        s += __shfl_xor_sync(0xffffffffu, s, 1);
        if (l16 == 0) g_Dv[row] = s;
    }
}

// ============================================================================
// Flash attention v9.1: round-13 v9 + causal work-skip on final tiles.
//  - S fragment skip: c0+cf > i0+wm*16+15 (fully masked for quad's rows)
//  - band skip: nb > jjmax, jjmax = min(127, i0+63-c0)+63 (gather never reads)
//  - PV granule skip: c0+kg8*4 > i0+63 (P identically zero there)
// ============================================================================
#define FL_SMEM_FLOATS 50240

__device__ __forceinline__ void bar_named(int id) {
    asm volatile("bar.sync %0, 128;" :: "r"(id));
}

__global__ void __launch_bounds__(512, 1) k_flash() {
    extern __shared__ float sm[];
    float* Brl  = sm + 36864;
    float* dsl  = sm + 49664;
    float* cks  = sm + 49856;
    float* mred = sm + 49984;
    uint32_t baseQ  = smem_u32(sm);
    uint32_t baseKb[2] = { smem_u32(sm + 4096), smem_u32(sm + 12288) };
    uint32_t baseVb[2] = { smem_u32(sm + 20480), smem_u32(sm + 28672) };
    uint32_t baseQm = smem_u32(sm + 36864);
    uint32_t* ksbuf[2] = { (uint32_t*)(sm + 4096), (uint32_t*)(sm + 12288) };

    int tid = threadIdx.x, warp = tid >> 5, lane = tid & 31;
    int wm = warp >> 2, wn = warp & 3, g = lane >> 2, tg = lane & 3;
    int nh = blockIdx.y, n = nh >> 4, h = nh & 15;
    int i0 = (int)(gridDim.x - 1 - blockIdx.x) * 64;
    int r0 = wm * 16 + g, r1 = r0 + 8;

    const float* qg  = g_q  + (size_t)n * LS * DS + h * HDM;
    const float* kg  = g_k  + (size_t)n * LS * DS + h * HDM;
    const float* vg  = g_vT + (size_t)(n * NHD + h) * HDM * LS;
    const float* ckb = g_ck + nh * LS;
    const float* Db  = g_Dv + h * LS;

    int ntiles = (i0 >> 7) + 1;

#pragma unroll
    for (int it = 0; it < 2; it++) {
        int f = tid + it * 512, row = f >> 4, c4 = f & 15;
        cp16(baseQ + (uint32_t)((row * 16 + (c4 ^ swz3(row))) << 4),
             &qg[(size_t)(i0 + row) * DS + c4 * 4]);
    }
#pragma unroll
    for (int it = 0; it < 4; it++) {
        int f = tid + it * 512;
        int krow = f >> 4, kc4 = f & 15;
        cp16(baseKb[0] + (uint32_t)((krow * 16 + (kc4 ^ swz3(krow))) << 4),
             &kg[(size_t)krow * DS + kc4 * 4]);
        int x = f >> 5, vc4 = f & 31;
        cp16(baseVb[0] + (uint32_t)((x * 32 + (vc4 ^ swz3(x))) << 4),
             &vg[(size_t)x * LS + vc4 * 4]);
    }
    asm volatile("cp.async.commit_group;" ::: "memory");

    float m0 = -INFINITY, m1 = -INFINITY;
    float l0 = 0.f, l1 = 0.f;
    float acco[2][4];
#pragma unroll
    for (int nt = 0; nt < 2; nt++)
#pragma unroll
        for (int e = 0; e < 4; e++) acco[nt][e] = 0.f;

    for (int jt = 0; jt < ntiles; jt++) {
        int c0 = jt * 128;
        int R0 = (LS - 1) + c0 - i0;
        int cur = jt & 1, nxt = cur ^ 1;
        bool has_next = (jt + 1 < ntiles);
        int cl_lim = i0 + 63 - c0;                         // >=127 means full tile
        int jjmax  = (cl_lim < 127 ? cl_lim : 127) + 63;   // band cols the gather reads
        int rlim   = i0 + wm * 16 + 15 - c0;               // quad's max unmasked cl
        __syncthreads();

#pragma unroll
        for (int it = 0; it < 6; it++) {
            int f = tid + it * 512, j = f >> 4, c4 = f & 15;
            int src = R0 - 63 + j;
            src = src < 0 ? 0 : (src > LS - 1 ? LS - 1 : src);
            cp16(baseQm + (uint32_t)((j * 16 + (c4 ^ swz3(j))) << 4),
                 &g_Qm[(size_t)src * DS + h * HDM + c4 * 4]);
        }
        asm volatile("cp.async.commit_group;" ::: "memory");

        if (has_next) {
            int c1 = c0 + 128;
#pragma unroll
            for (int it = 0; it < 4; it++) {
                int f = tid + it * 512;
                int krow = f >> 4, kc4 = f & 15;
                cp16(baseKb[nxt] + (uint32_t)((krow * 16 + (kc4 ^ swz3(krow))) << 4),
                     &kg[(size_t)(c1 + krow) * DS + kc4 * 4]);
                int x = f >> 5, vc4 = f & 31;
                cp16(baseVb[nxt] + (uint32_t)((x * 32 + (vc4 ^ swz3(x))) << 4),
                     &vg[(size_t)x * LS + c1 + vc4 * 4]);
            }
            asm volatile("cp.async.commit_group;" ::: "memory");
        }

        if (tid < 192) {
            int idx = R0 - 63 + tid;
            dsl[tid] = (idx >= 0 && idx < LS) ? Db[idx] : 0.f;
        }
        if (tid >= 256 && tid < 384) {
            int t = tid - 256;
            cks[t] = ckb[c0 + t];
        }

        if (has_next) asm volatile("cp.async.wait_group 2;" ::: "memory");
        else          asm volatile("cp.async.wait_group 1;" ::: "memory");
        __syncthreads();

        float sc[4][4];
#pragma unroll
        for (int nt = 0; nt < 4; nt++)
#pragma unroll
            for (int e = 0; e < 4; e++) sc[nt][e] = 0.f;
        uint32_t aq[8][4];
#pragma unroll
        for (int kg8 = 0; kg8 < 16; kg8 += 2) {
            ldsmA<16>(aq[kg8 >> 1], baseQ, wm * 16, kg8, lane);
#pragma unroll
            for (int p = 0; p < 2; p++) {
                if (wn * 32 + p * 16 <= rlim) {            // fragment has live cols
                    uint32_t bk[4];
                    ldsmB<16>(bk, baseKb[cur], wn * 32 + p * 16, kg8, lane);
                    mma_tf32(sc[2*p],   aq[kg8>>1][0], aq[kg8>>1][1], aq[kg8>>1][2], aq[kg8>>1][3], bk[0], bk[1]);
                    mma_tf32(sc[2*p+1], aq[kg8>>1][0], aq[kg8>>1][1], aq[kg8>>1][2], aq[kg8>>1][3], bk[2], bk[3]);
                }
            }
        }

        if (has_next) asm volatile("cp.async.wait_group 1;" ::: "memory");
        else          asm volatile("cp.async.wait_group 0;" ::: "memory");
        __syncthreads();

        float br[6][4];
#pragma unroll
        for (int nt = 0; nt < 6; nt++)
#pragma unroll
            for (int e = 0; e < 4; e++) br[nt][e] = 0.f;
#pragma unroll
        for (int kg8 = 0; kg8 < 16; kg8 += 2) {
#pragma unroll
            for (int p = 0; p < 3; p++) {
                int nb = wn * 48 + p * 16;
                if (nb <= jjmax) {                         // gather never reads past jjmax
                    uint32_t bq[4];
                    ldsmB<16>(bq, baseQm, nb, kg8, lane);
                    mma_tf32(br[2*p],   aq[kg8>>1][0], aq[kg8>>1][1], aq[kg8>>1][2], aq[kg8>>1][3], bq[0], bq[1]);
                    mma_tf32(br[2*p+1], aq[kg8>>1][0], aq[kg8>>1][1], aq[kg8>>1][2], aq[kg8>>1][3], bq[2], bq[3]);
                }
            }
        }
        __syncthreads();

#pragma unroll
        for (int nt = 0; nt < 6; nt++) {
            int nb = wn * 48 + (nt >> 1) * 16;
            if (nb <= jjmax) {
                int col = wn * 48 + nt * 8 + tg * 2;
                float d0 = dsl[col], d1 = dsl[col + 1];
                *(float2*)&Brl[r0 * 200 + col] = make_float2(br[nt][0] + d0, br[nt][1] + d1);
                *(float2*)&Brl[r1 * 200 + col] = make_float2(br[nt][2] + d0, br[nt][3] + d1);
            }
        }
        bar_named(wm + 1);

#pragma unroll
        for (int nt = 0; nt < 4; nt++) {
            int cl0 = wn * 32 + nt * 8 + tg * 2;
#pragma unroll
            for (int e = 0; e < 4; e++) {
                int r  = (e >= 2) ? r1 : r0;
                int cl = cl0 + (e & 1);
                float v;
                if (c0 + cl > i0 + r) {
                    v = -INFINITY;
                } else {
                    float bd = Brl[r * 200 + (cl - r + 63)];
                    v = sc[nt][e] + cks[cl] + bd;
                    if (c0 + cl == i0 + r) v += bd;
                }
                sc[nt][e] = v;
            }
        }

        float mx0 = -INFINITY, mx1 = -INFINITY;
#pragma unroll
        for (int nt = 0; nt < 4; nt++) {
            mx0 = fmaxf(mx0, fmaxf(sc[nt][0], sc[nt][1]));
            mx1 = fmaxf(mx1, fmaxf(sc[nt][2], sc[nt][3]));
        }
        mx0 = fmaxf(mx0, __shfl_xor_sync(0xffffffffu, mx0, 1));
        mx0 = fmaxf(mx0, __shfl_xor_sync(0xffffffffu, mx0, 2));
        mx1 = fmaxf(mx1, __shfl_xor_sync(0xffffffffu, mx1, 1));
        mx1 = fmaxf(mx1, __shfl_xor_sync(0xffffffffu, mx1, 2));
        if (tg == 0) { mred[r0 * 4 + wn] = mx0; mred[r1 * 4 + wn] = mx1; }
        bar_named(wm + 1);
        float4 ma = *(const float4*)&mred[r0 * 4];
        float4 mb = *(const float4*)&mred[r1 * 4];
        float m0n = fmaxf(m0, fmaxf(fmaxf(ma.x, ma.y), fmaxf(ma.z, ma.w)));
        float m1n = fmaxf(m1, fmaxf(fmaxf(mb.x, mb.y), fmaxf(mb.z, mb.w)));
        float a0 = __expf(m0 - m0n), a1 = __expf(m1 - m1n);
        m0 = m0n; m1 = m1n;

        uint32_t* Sp = ksbuf[cur];
        float ls0 = 0.f, ls1 = 0.f;
#pragma unroll
        for (int nt = 0; nt < 4; nt++) {
            int cl0 = wn * 32 + nt * 8 + tg * 2;
            float e0 = __expf(sc[nt][0] - m0n);
            float e1 = __expf(sc[nt][1] - m0n);
            float e2 = __expf(sc[nt][2] - m1n);
            float e3 = __expf(sc[nt][3] - m1n);
            ls0 += e0 + e1; ls1 += e2 + e3;
            uint2 u0; u0.x = f2tf(e0); u0.y = f2tf(e1);
            uint2 u1; u1.x = f2tf(e2); u1.y = f2tf(e3);
            int base0 = r0 * 128 + (((cl0 >> 2) ^ swz3(r0)) << 2) + (cl0 & 3);
            int base1 = r1 * 128 + (((cl0 >> 2) ^ swz3(r1)) << 2) + (cl0 & 3);
            *(uint2*)&Sp[base0] = u0;
            *(uint2*)&Sp[base1] = u1;
        }
        l0 = l0 * a0 + ls0;
        l1 = l1 * a1 + ls1;

#pragma unroll
        for (int nt = 0; nt < 2; nt++) {
            acco[nt][0] *= a0; acco[nt][1] *= a0;
            acco[nt][2] *= a1; acco[nt][3] *= a1;
        }
        bar_named(wm + 1);

#pragma unroll
        for (int kg8 = 0; kg8 < 32; kg8 += 2) {
            if (kg8 * 4 <= cl_lim) {                       // P granule nonzero
                uint32_t af[4], bv[4];
                ldsmA<32>(af, baseKb[cur], wm * 16, kg8, lane);
                ldsmB<32>(bv, baseVb[cur], wn * 16, kg8, lane);
                mma_tf32(acco[0], af[0], af[1], af[2], af[3], bv[0], bv[1]);
                mma_tf32(acco[1], af[0], af[1], af[2], af[3], bv[2], bv[3]);
            }
        }
    }

    l0 += __shfl_xor_sync(0xffffffffu, l0, 1);
    l0 += __shfl_xor_sync(0xffffffffu, l0, 2);
    l1 += __shfl_xor_sync(0xffffffffu, l1, 1);
    l1 += __shfl_xor_sync(0xffffffffu, l1, 2);
    bar_named(wm + 1);
    if (tg == 0) { mred[r0 * 4 + wn] = l0; mred[r1 * 4 + wn] = l1; }
    bar_named(wm + 1);
    float4 la = *(const float4*)&mred[r0 * 4];
    float4 lb = *(const float4*)&mred[r1 * 4];
    float i1 = 1.f / (la.x + la.y + la.z + la.w);
    float i2 = 1.f / (lb.x + lb.y + lb.z + lb.w);
#pragma unroll
    for (int nt = 0; nt < 2; nt++) {
        int col = h * HDM + wn * 16 + nt * 8 + tg * 2;
        size_t w1 = (size_t)(n * LS + i0 + r0) * DS + col;
        size_t w2 = w1 + (size_t)8 * DS;
        *(float2*)&g_O[w1] = make_float2(rndtf(acco[nt][0] * i1), rndtf(acco[nt][1] * i1));
        *(float2*)&g_O[w2] = make_float2(rndtf(acco[nt][2] * i2), rndtf(acco[nt][3] * i2));
    }
}

// ---------------- row layernorm ---------------------------------------------
__global__ void k_ln(const float* __restrict__ g, const float* __restrict__ b,
                     float* __restrict__ out) {
    int row = blockIdx.x, tid = threadIdx.x;
    const float* z = g_Z + (size_t)row * DS;
    __shared__ float red[256];
    __shared__ float s_mu, s_rstd;
    float4 zv = *(const float4*)&z[tid * 4];
    float s = zv.x + zv.y + zv.z + zv.w;
    red[tid] = s; __syncthreads();
    for (int o = 128; o > 0; o >>= 1) { if (tid < o) red[tid] += red[tid + o]; __syncthreads(); }
    if (tid == 0) s_mu = red[0] * (1.f / DS);
    __syncthreads();
    float mu = s_mu;
    float dx = zv.x - mu, dy = zv.y - mu, dz = zv.z - mu, dw = zv.w - mu;
    red[tid] = dx*dx + dy*dy + dz*dz + dw*dw; __syncthreads();
    for (int o = 128; o > 0; o >>= 1) { if (tid < o) red[tid] += red[tid + o]; __syncthreads(); }
    if (tid == 0) s_rstd = rsqrtf(red[0] * (1.f / DS) + 1e-5f);
    __syncthreads();
    float rstd = s_rstd;
    float4 gv = *(const float4*)&g[tid * 4];
    float4 bv = *(const float4*)&b[tid * 4];
    float4 ov;
    ov.x = dx * rstd * gv.x + bv.x;
    ov.y = dy * rstd * gv.y + bv.y;
    ov.z = dz * rstd * gv.z + bv.z;
    ov.w = dw * rstd * gv.w + bv.w;
    *(float4*)&out[(size_t)row * DS + tid * 4] = ov;
}

// ---------------- launch ------------------------------------------------------
extern "C" void kernel_launch(void* const* d_in, const int* in_sizes, int n_in,
                              void* d_out, int out_size) {
    const float* X   = (const float*)d_in[0];
    const float* Y   = (const float*)d_in[1];
    const float* Wq  = (const float*)d_in[4];
    const float* We  = (const float*)d_in[5];
    const float* Wv  = (const float*)d_in[6];
    const float* Wr  = (const float*)d_in[7];
    const float* cb  = (const float*)d_in[8];
    const float* pb  = (const float*)d_in[9];
    const float* Wo  = (const float*)d_in[10];
    const float* Wob = (const float*)d_in[11];
    const float* lng = (const float*)d_in[12];
    const float* lnb = (const float*)d_in[13];
    float* out = (float*)d_out;

    float *Op, *Zp, *WoRp;
    cudaGetSymbolAddress((void**)&Op, g_O);
    cudaGetSymbolAddress((void**)&Zp, g_Z);
    cudaGetSymbolAddress((void**)&WoRp, g_WoR);

    cudaFuncSetAttribute(k_flash, cudaFuncAttributeMaxDynamicSharedMemorySize,
                         FL_SMEM_FLOATS * (int)sizeof(float));
    cudaFuncSetAttribute(k_mma<1>, cudaFuncAttributeMaxDynamicSharedMemorySize,
                         GEMM_SMEM_BYTES);
    cudaFuncSetAttribute(k_mma_proj, cudaFuncAttributeMaxDynamicSharedMemorySize,
                         GEMM_SMEM_BYTES);

    // merged prep: rope + weight transposes + rounded copies
    int prep_blocks = 2048 + 4096 + (2 * (NLR * DS / 4) + DS * DS / 4 + 255) / 256;
    k_prep<<<prep_blocks, 256>>>(X, Y, Wq, We, Wv, Wr, Wo);

    // fused projections: q/k/vT (z=0..2) + Qm = R@Wr (z=3)
    k_mma_proj<<<dim3(DS/128, NLR/128, 4), 256, GEMM_SMEM_BYTES>>>();

    // ck + Dv tables
    k_tabs<<<(NB * NHD * LS + NHD * LS) / 16, 256>>>(cb, pb);

    // fused causal attention (64x128 tiles + causal work-skip)
    k_flash<<<dim3(LS / 64, NB * NHD), 512, FL_SMEM_FLOATS * sizeof(float)>>>();

    // Z = X + O @ Wo^T + Wo_b
    k_mma<1><<<dim3(DS/128, NLR/128), 256, GEMM_SMEM_BYTES>>>(
        Op, DS, WoRp, DS, Zp, DS, DS, Wob, X);

    // layernorm -> out
    k_ln<<<NLR, 256>>>(lng, lnb, out);
}

// round 16
// speedup vs baseline: 1.1660x; 1.1660x over previous
#include <cuda_runtime.h>
#include <math.h>
#include <stdint.h>

// Problem constants (hardcoded from setup_inputs)
#define NB 2
#define LS 1024
#define DS 1024
#define NHD 16
#define HDM 64
#define NLR (NB*LS)   // 2048

// ---------------- scratch (__device__ globals; no allocation allowed) -------
__device__ float g_q [NLR*DS];          // 8 MB  : X@Wq, tf32-rounded
__device__ float g_k [NLR*DS];          // 8 MB  : Y@We, tf32-rounded
__device__ float g_vT[NLR*DS];          // 8 MB  : Y@Wv, [n][h][x][c], tf32-rounded
__device__ float g_R [LS*DS];           // 4 MB  : matrix_r rows 0..L-1, tf32-rounded
__device__ float g_Qm[LS*DS];           // 4 MB  : R[0:L]@Wr, tf32-rounded
__device__ float g_WT[4*DS*DS];         // 16 MB : Wq/We/Wv/Wr transposed+rounded [n][k]
__device__ float g_Xr[NLR*DS];          // 8 MB  : X tf32-rounded
__device__ float g_Yr[NLR*DS];          // 8 MB  : Y tf32-rounded
__device__ float g_WoR[DS*DS];          // 4 MB  : Wo tf32-rounded
__device__ float g_ck[NB*NHD*LS];       // cb_h . k_c
__device__ float g_Dv[NHD*LS];          // pb_h . Qm_r
__device__ float g_O [NLR*DS];          // attention output, tf32-rounded
__device__ float g_Z [NLR*DS];          // pre-layernorm

// ---------------- helpers ----------------------------------------------------
__device__ __forceinline__ uint32_t f2tf(float f) {
    uint32_t u; asm("cvt.rna.tf32.f32 %0, %1;" : "=r"(u) : "f"(f)); return u;
}
__device__ __forceinline__ float rndtf(float f) { return __uint_as_float(f2tf(f)); }
__device__ __forceinline__ int swz3(int r) { return (r ^ (r >> 2)) & 7; }
__device__ __forceinline__ uint32_t smem_u32(const void* p) {
    return (uint32_t)__cvta_generic_to_shared(p);
}
__device__ __forceinline__ void cp16(uint32_t saddr, const void* g) {
    asm volatile("cp.async.cg.shared.global [%0], [%1], 16;" :: "r"(saddr), "l"(g));
}

// ============================================================================
// merged prep kernel: blocks [0,2048) rope | [2048,6144) weight-T | rest rnd
// ============================================================================
__global__ void k_prep(const float* __restrict__ X, const float* __restrict__ Y,
                       const float* __restrict__ W0, const float* __restrict__ W1,
                       const float* __restrict__ W2, const float* __restrict__ W3,
                       const float* __restrict__ Wo) {
    int b = blockIdx.x;
    if (b < 2048) {
        int idx = b * 256 + threadIdx.x;
        int r = idx / (DS/2), j = idx % (DS/2);
        float ex   = -(float)(2 * j) * (13.287712379549449f / (float)DS);
        float invf = exp2f(ex);
        float ang  = (float)(r - (LS - 1)) * invf;
        float s, c;
        sincosf(ang, &s, &c);
        g_R[r*DS + 2*j]   = rndtf(s);
        g_R[r*DS + 2*j+1] = rndtf(c);
    } else if (b < 6144) {
        __shared__ float t[32][33];
        int b2 = b - 2048;
        int z = b2 >> 10, rem = b2 & 1023;
        int bx = (rem & 31) * 32, by = (rem >> 5) * 32;
        const float* src = (z == 0) ? W0 : (z == 1) ? W1 : (z == 2) ? W2 : W3;
        float* dst = g_WT + (size_t)z * DS * DS;
        int tx = threadIdx.x & 31, ty4 = (threadIdx.x >> 5) * 4;
#pragma unroll
        for (int i = 0; i < 4; i++)
            t[ty4 + i][tx] = src[(size_t)(by + ty4 + i) * DS + bx + tx];
        __syncthreads();
#pragma unroll
        for (int i = 0; i < 4; i++)
            dst[(size_t)(bx + ty4 + i) * DS + by + tx] = rndtf(t[tx][ty4 + i]);
    } else {
        int idx = (b - 6144) * 256 + threadIdx.x;
        const int NX = NLR * DS / 4;
        const int NW = DS * DS / 4;
        const float4* src; float* dst; int off;
        if (idx < NX)            { src = (const float4*)X;  dst = g_Xr;  off = idx; }
        else if (idx < 2 * NX)   { src = (const float4*)Y;  dst = g_Yr;  off = idx - NX; }
        else if (idx < 2*NX+NW)  { src = (const float4*)Wo; dst = g_WoR; off = idx - 2*NX; }
        else return;
        float4 v = src[off];
        v.x = rndtf(v.x); v.y = rndtf(v.y); v.z = rndtf(v.z); v.w = rndtf(v.w);
        *(float4*)&dst[(size_t)off * 4] = v;
    }
}

// ---------------- MMA / ldmatrix ----------------------------------------------
__device__ __forceinline__ void mma_tf32(float c[4],
    uint32_t a0, uint32_t a1, uint32_t a2, uint32_t a3,
    uint32_t b0, uint32_t b1)
{
    asm volatile(
        "mma.sync.aligned.m16n8k8.row.col.f32.tf32.tf32.f32 "
        "{%0,%1,%2,%3}, {%4,%5,%6,%7}, {%8,%9}, {%0,%1,%2,%3};"
        : "+f"(c[0]), "+f"(c[1]), "+f"(c[2]), "+f"(c[3])
        : "r"(a0), "r"(a1), "r"(a2), "r"(a3), "r"(b0), "r"(b1));
}

template<int PG>
__device__ __forceinline__ void ldsmA(uint32_t fr[4], uint32_t base, int mb, int kg, int lane) {
    int t = lane >> 3, tr = lane & 7;
    int row = mb + ((t & 1) << 3) + tr;
    int cg  = (kg + (t >> 1)) ^ swz3(row);
    uint32_t a = base + (uint32_t)((row * PG + cg) << 4);
    asm volatile("ldmatrix.sync.aligned.m8n8.x4.shared.b16 {%0,%1,%2,%3}, [%4];"
        : "=r"(fr[0]), "=r"(fr[1]), "=r"(fr[2]), "=r"(fr[3]) : "r"(a));
}
template<int PG>
__device__ __forceinline__ void ldsmB(uint32_t fr[4], uint32_t base, int nb, int kg, int lane) {
    int t = lane >> 3, tr = lane & 7;
    int row = nb + ((t >> 1) << 3) + tr;
    int cg  = (kg + (t & 1)) ^ swz3(row);
    uint32_t a = base + (uint32_t)((row * PG + cg) << 4);
    asm volatile("ldmatrix.sync.aligned.m8n8.x4.shared.b16 {%0,%1,%2,%3}, [%4];"
        : "=r"(fr[0]), "=r"(fr[1]), "=r"(fr[2]), "=r"(fr[3]) : "r"(a));
}

// ============================================================================
// TF32 GEMM v3 (unchanged): CTA 128x128, BK=32, 3-stage cp.async
// ============================================================================
#define GEMM_STAGES 3
#define GEMM_SMEM_BYTES (GEMM_STAGES * 32768)

template<int EPIM>
__device__ __forceinline__ void mma_gemm_body(
    const float* __restrict__ A, int lda,
    const float* __restrict__ B, int ldb,
    float* __restrict__ C, int ldc, int K,
    int m0, int n0,
    const float* __restrict__ bias, const float* __restrict__ res,
    uint32_t* smem)
{
    int tid  = threadIdx.x;
    int warp = tid >> 5, lane = tid & 31;
    int wm = warp >> 1, wn = warp & 1;
    int g = lane >> 2, tg = lane & 3;
    uint32_t base = smem_u32(smem);
    int nch = K >> 5;

    float acc[2][8][4];
#pragma unroll
    for (int mt = 0; mt < 2; mt++)
#pragma unroll
        for (int nt = 0; nt < 8; nt++)
#pragma unroll
            for (int c = 0; c < 4; c++) acc[mt][nt][c] = 0.f;

    auto fill = [&](int kc, int st) {
        uint32_t bA = base + (uint32_t)st * 32768, bB = bA + 16384;
        int kk = kc * 32;
#pragma unroll
        for (int it = 0; it < 4; it++) {
            int f = tid + it * 256, row = f >> 3, c4 = f & 7;
            uint32_t so = (uint32_t)((row * 8 + (c4 ^ swz3(row))) << 4);
            cp16(bA + so, &A[(size_t)(m0 + row) * lda + kk + c4 * 4]);
            cp16(bB + so, &B[(size_t)(n0 + row) * ldb + kk + c4 * 4]);
        }
        asm volatile("cp.async.commit_group;" ::: "memory");
    };

    fill(0, 0);
    if (nch > 1) fill(1, 1);

    for (int j = 0; j < nch; j++) {
        if (j + 1 < nch) asm volatile("cp.async.wait_group 1;" ::: "memory");
        else             asm volatile("cp.async.wait_group 0;" ::: "memory");
        __syncthreads();
        if (j + 2 < nch) fill(j + 2, (j + 2) % GEMM_STAGES);
        uint32_t bA = base + (uint32_t)(j % GEMM_STAGES) * 32768;
        uint32_t bB = bA + 16384;
#pragma unroll
        for (int kg = 0; kg < 8; kg += 2) {
            uint32_t af[2][4], bf[4][4];
            ldsmA<8>(af[0], bA, wm * 32,      kg, lane);
            ldsmA<8>(af[1], bA, wm * 32 + 16, kg, lane);
#pragma unroll
            for (int p = 0; p < 4; p++)
                ldsmB<8>(bf[p], bB, wn * 64 + p * 16, kg, lane);
#pragma unroll
            for (int mt = 0; mt < 2; mt++)
#pragma unroll
                for (int p = 0; p < 4; p++) {
                    mma_tf32(acc[mt][2*p],   af[mt][0], af[mt][1], af[mt][2], af[mt][3],
                             bf[p][0], bf[p][1]);
                    mma_tf32(acc[mt][2*p+1], af[mt][0], af[mt][1], af[mt][2], af[mt][3],
                             bf[p][2], bf[p][3]);
                }
        }
    }

#pragma unroll
    for (int mt = 0; mt < 2; mt++) {
        int row = m0 + wm * 32 + mt * 16 + g;
#pragma unroll
        for (int nt = 0; nt < 8; nt++) {
            int col = n0 + wn * 64 + nt * 8 + tg * 2;
            if (EPIM == 2) {
                int n_ = row >> 10, c_ = row & 1023;
                size_t b0 = ((size_t)n_ * (NHD * HDM) + col) * LS + c_;
                g_vT[b0]          = rndtf(acc[mt][nt][0]);
                g_vT[b0 + LS]     = rndtf(acc[mt][nt][1]);
                g_vT[b0 + 8]      = rndtf(acc[mt][nt][2]);
                g_vT[b0 + LS + 8] = rndtf(acc[mt][nt][3]);
            } else {
                float2 v0, v1;
                if (EPIM == 1) {
                    v0.x = acc[mt][nt][0] + bias[col]     + res[(size_t)row * ldc + col];
                    v0.y = acc[mt][nt][1] + bias[col + 1] + res[(size_t)row * ldc + col + 1];
                    v1.x = acc[mt][nt][2] + bias[col]     + res[(size_t)(row + 8) * ldc + col];
                    v1.y = acc[mt][nt][3] + bias[col + 1] + res[(size_t)(row + 8) * ldc + col + 1];
                } else {
                    v0.x = rndtf(acc[mt][nt][0]); v0.y = rndtf(acc[mt][nt][1]);
                    v1.x = rndtf(acc[mt][nt][2]); v1.y = rndtf(acc[mt][nt][3]);
                }
                *(float2*)&C[(size_t)row * ldc + col]       = v0;
                *(float2*)&C[(size_t)(row + 8) * ldc + col] = v1;
            }
        }
    }
}

template<int EPIM>
__global__ void __launch_bounds__(256, 2) k_mma(
    const float* __restrict__ A, int lda,
    const float* __restrict__ B, int ldb,
    float* __restrict__ C, int ldc, int K,
    const float* __restrict__ bias, const float* __restrict__ res)
{
    extern __shared__ uint32_t smemu[];
    mma_gemm_body<EPIM>(A, lda, B, ldb, C, ldc, K,
                        blockIdx.y * 128, blockIdx.x * 128, bias, res, smemu);
}

__global__ void __launch_bounds__(256, 2) k_mma_proj()
{
    extern __shared__ uint32_t smemu[];
    int z = blockIdx.z;
    if (z == 3 && blockIdx.y >= LS / 128) return;
    const float* A = (z == 0) ? g_Xr : (z == 3) ? g_R : g_Yr;
    const float* B = g_WT + (size_t)z * DS * DS;
    if (z == 2) {
        mma_gemm_body<2>(A, DS, B, DS, nullptr, DS, DS,
                         blockIdx.y * 128, blockIdx.x * 128, nullptr, nullptr, smemu);
    } else {
        float* C = (z == 0) ? g_q : (z == 1) ? g_k : g_Qm;
        mma_gemm_body<0>(A, DS, B, DS, C, DS, DS,
                         blockIdx.y * 128, blockIdx.x * 128, nullptr, nullptr, smemu);
    }
}

// ---------------- small dot-product tables ----------------------------------
__global__ void k_tabs(const float* __restrict__ cb, const float* __restrict__ pb) {
    int l16  = threadIdx.x & 15;
    int wrow = (int)blockIdx.x * 16 + (threadIdx.x >> 4);
    float4 w, k;
    if (blockIdx.x < (NB * NHD * LS / 16)) {
        int n = wrow >> 14, h = (wrow >> 10) & 15, c = wrow & 1023;
        w = *(const float4*)&cb[h * HDM + l16 * 4];
        k = *(const float4*)&g_k[(size_t)(n * LS + c) * DS + h * HDM + l16 * 4];
        float s = w.x*k.x + w.y*k.y + w.z*k.z + w.w*k.w;
        s += __shfl_xor_sync(0xffffffffu, s, 8);
        s += __shfl_xor_sync(0xffffffffu, s, 4);
        s += __shfl_xor_sync(0xffffffffu, s, 2);
        s += __shfl_xor_sync(0xffffffffu, s, 1);
        if (l16 == 0) g_ck[wrow] = s;
    } else {
        int row = wrow - NB * NHD * LS;
        int h = row >> 10, r = row & 1023;
        w = *(const float4*)&pb[h * HDM + l16 * 4];
        k = *(const float4*)&g_Qm[(size_t)r * DS + h * HDM + l16 * 4];
        float s = w.x*k.x + w.y*k.y + w.z*k.z + w.w*k.w;
        s += __shfl_xor_sync(0xffffffffu, s, 8);
        s += __shfl_xor_sync(0xffffffffu, s, 4);
        s += __shfl_xor_sync(0xffffffffu, s, 2);
        s += __shfl_xor_sync(0xffffffffu, s, 1);
        if (l16 == 0) g_Dv[row] = s;
    }
}

// ============================================================================
// Flash attention v9.2: round-13 v9 main loop (branch-free, byte-identical),
// final tile PEELED with causal work-skip guards (validated in R15).
// ============================================================================
#define FL_SMEM_FLOATS 50240

__device__ __forceinline__ void bar_named(int id) {
    asm volatile("bar.sync %0, 128;" :: "r"(id));
}

__global__ void __launch_bounds__(512, 1) k_flash() {
    extern __shared__ float sm[];
    float* Brl  = sm + 36864;
    float* dsl  = sm + 49664;
    float* cks  = sm + 49856;
    float* mred = sm + 49984;
    uint32_t baseQ  = smem_u32(sm);
    uint32_t baseKb[2] = { smem_u32(sm + 4096), smem_u32(sm + 12288) };
    uint32_t baseVb[2] = { smem_u32(sm + 20480), smem_u32(sm + 28672) };
    uint32_t baseQm = smem_u32(sm + 36864);
    uint32_t* ksbuf[2] = { (uint32_t*)(sm + 4096), (uint32_t*)(sm + 12288) };

    int tid = threadIdx.x, warp = tid >> 5, lane = tid & 31;
    int wm = warp >> 2, wn = warp & 3, g = lane >> 2, tg = lane & 3;
    int nh = blockIdx.y, n = nh >> 4, h = nh & 15;
    int i0 = (int)(gridDim.x - 1 - blockIdx.x) * 64;
    int r0 = wm * 16 + g, r1 = r0 + 8;

    const float* qg  = g_q  + (size_t)n * LS * DS + h * HDM;
    const float* kg  = g_k  + (size_t)n * LS * DS + h * HDM;
    const float* vg  = g_vT + (size_t)(n * NHD + h) * HDM * LS;
    const float* ckb = g_ck + nh * LS;
    const float* Db  = g_Dv + h * LS;

    int ntiles = (i0 >> 7) + 1;

#pragma unroll
    for (int it = 0; it < 2; it++) {
        int f = tid + it * 512, row = f >> 4, c4 = f & 15;
        cp16(baseQ + (uint32_t)((row * 16 + (c4 ^ swz3(row))) << 4),
             &qg[(size_t)(i0 + row) * DS + c4 * 4]);
    }
#pragma unroll
    for (int it = 0; it < 4; it++) {
        int f = tid + it * 512;
        int krow = f >> 4, kc4 = f & 15;
        cp16(baseKb[0] + (uint32_t)((krow * 16 + (kc4 ^ swz3(krow))) << 4),
             &kg[(size_t)krow * DS + kc4 * 4]);
        int x = f >> 5, vc4 = f & 31;
        cp16(baseVb[0] + (uint32_t)((x * 32 + (vc4 ^ swz3(x))) << 4),
             &vg[(size_t)x * LS + vc4 * 4]);
    }
    asm volatile("cp.async.commit_group;" ::: "memory");

    float m0 = -INFINITY, m1 = -INFINITY;
    float l0 = 0.f, l1 = 0.f;
    float acco[2][4];
#pragma unroll
    for (int nt = 0; nt < 2; nt++)
#pragma unroll
        for (int e = 0; e < 4; e++) acco[nt][e] = 0.f;

    // -------- main loop: non-final tiles, branch-free (round-13 body) --------
    for (int jt = 0; jt < ntiles - 1; jt++) {
        int c0 = jt * 128;
        int R0 = (LS - 1) + c0 - i0;
        int cur = jt & 1, nxt = cur ^ 1;
        __syncthreads();

#pragma unroll
        for (int it = 0; it < 6; it++) {
            int f = tid + it * 512, j = f >> 4, c4 = f & 15;
            int src = R0 - 63 + j;
            src = src < 0 ? 0 : (src > LS - 1 ? LS - 1 : src);
            cp16(baseQm + (uint32_t)((j * 16 + (c4 ^ swz3(j))) << 4),
                 &g_Qm[(size_t)src * DS + h * HDM + c4 * 4]);
        }
        asm volatile("cp.async.commit_group;" ::: "memory");

        {
            int c1 = c0 + 128;
#pragma unroll
            for (int it = 0; it < 4; it++) {
                int f = tid + it * 512;
                int krow = f >> 4, kc4 = f & 15;
                cp16(baseKb[nxt] + (uint32_t)((krow * 16 + (kc4 ^ swz3(krow))) << 4),
                     &kg[(size_t)(c1 + krow) * DS + kc4 * 4]);
                int x = f >> 5, vc4 = f & 31;
                cp16(baseVb[nxt] + (uint32_t)((x * 32 + (vc4 ^ swz3(x))) << 4),
                     &vg[(size_t)x * LS + c1 + vc4 * 4]);
            }
            asm volatile("cp.async.commit_group;" ::: "memory");
        }

        if (tid < 192) {
            int idx = R0 - 63 + tid;
            dsl[tid] = (idx >= 0 && idx < LS) ? Db[idx] : 0.f;
        }
        if (tid >= 256 && tid < 384) {
            int t = tid - 256;
            cks[t] = ckb[c0 + t];
        }

        asm volatile("cp.async.wait_group 2;" ::: "memory");
        __syncthreads();

        float sc[4][4];
#pragma unroll
        for (int nt = 0; nt < 4; nt++)
#pragma unroll
            for (int e = 0; e < 4; e++) sc[nt][e] = 0.f;
        uint32_t aq[8][4];
#pragma unroll
        for (int kg8 = 0; kg8 < 16; kg8 += 2) {
            ldsmA<16>(aq[kg8 >> 1], baseQ, wm * 16, kg8, lane);
#pragma unroll
            for (int p = 0; p < 2; p++) {
                uint32_t bk[4];
                ldsmB<16>(bk, baseKb[cur], wn * 32 + p * 16, kg8, lane);
                mma_tf32(sc[2*p],   aq[kg8>>1][0], aq[kg8>>1][1], aq[kg8>>1][2], aq[kg8>>1][3], bk[0], bk[1]);
                mma_tf32(sc[2*p+1], aq[kg8>>1][0], aq[kg8>>1][1], aq[kg8>>1][2], aq[kg8>>1][3], bk[2], bk[3]);
            }
        }

        asm volatile("cp.async.wait_group 1;" ::: "memory");
        __syncthreads();

        float br[6][4];
#pragma unroll
        for (int nt = 0; nt < 6; nt++)
#pragma unroll
            for (int e = 0; e < 4; e++) br[nt][e] = 0.f;
#pragma unroll
        for (int kg8 = 0; kg8 < 16; kg8 += 2) {
#pragma unroll
            for (int p = 0; p < 3; p++) {
                uint32_t bq[4];
                ldsmB<16>(bq, baseQm, wn * 48 + p * 16, kg8, lane);
                mma_tf32(br[2*p],   aq[kg8>>1][0], aq[kg8>>1][1], aq[kg8>>1][2], aq[kg8>>1][3], bq[0], bq[1]);
                mma_tf32(br[2*p+1], aq[kg8>>1][0], aq[kg8>>1][1], aq[kg8>>1][2], aq[kg8>>1][3], bq[2], bq[3]);
            }
        }
        __syncthreads();

#pragma unroll
        for (int nt = 0; nt < 6; nt++) {
            int col = wn * 48 + nt * 8 + tg * 2;
            float d0 = dsl[col], d1 = dsl[col + 1];
            *(float2*)&Brl[r0 * 200 + col] = make_float2(br[nt][0] + d0, br[nt][1] + d1);
            *(float2*)&Brl[r1 * 200 + col] = make_float2(br[nt][2] + d0, br[nt][3] + d1);
        }
        bar_named(wm + 1);

#pragma unroll
        for (int nt = 0; nt < 4; nt++) {
            int cl0 = wn * 32 + nt * 8 + tg * 2;
#pragma unroll
            for (int e = 0; e < 4; e++) {
                int r  = (e >= 2) ? r1 : r0;
                int cl = cl0 + (e & 1);
                // non-final tile: c0+cl <= c0+127 < i0, never masked, never diag
                float bd = Brl[r * 200 + (cl - r + 63)];
                sc[nt][e] = sc[nt][e] + cks[cl] + bd;
            }
        }

        float mx0 = -INFINITY, mx1 = -INFINITY;
#pragma unroll
        for (int nt = 0; nt < 4; nt++) {
            mx0 = fmaxf(mx0, fmaxf(sc[nt][0], sc[nt][1]));
            mx1 = fmaxf(mx1, fmaxf(sc[nt][2], sc[nt][3]));
        }
        mx0 = fmaxf(mx0, __shfl_xor_sync(0xffffffffu, mx0, 1));
        mx0 = fmaxf(mx0, __shfl_xor_sync(0xffffffffu, mx0, 2));
        mx1 = fmaxf(mx1, __shfl_xor_sync(0xffffffffu, mx1, 1));
        mx1 = fmaxf(mx1, __shfl_xor_sync(0xffffffffu, mx1, 2));
        if (tg == 0) { mred[r0 * 4 + wn] = mx0; mred[r1 * 4 + wn] = mx1; }
        bar_named(wm + 1);
        float4 ma = *(const float4*)&mred[r0 * 4];
        float4 mb = *(const float4*)&mred[r1 * 4];
        float m0n = fmaxf(m0, fmaxf(fmaxf(ma.x, ma.y), fmaxf(ma.z, ma.w)));
        float m1n = fmaxf(m1, fmaxf(fmaxf(mb.x, mb.y), fmaxf(mb.z, mb.w)));
        float a0 = __expf(m0 - m0n), a1 = __expf(m1 - m1n);
        m0 = m0n; m1 = m1n;

        uint32_t* Sp = ksbuf[cur];
        float ls0 = 0.f, ls1 = 0.f;
#pragma unroll
        for (int nt = 0; nt < 4; nt++) {
            int cl0 = wn * 32 + nt * 8 + tg * 2;
            float e0 = __expf(sc[nt][0] - m0n);
            float e1 = __expf(sc[nt][1] - m0n);
            float e2 = __expf(sc[nt][2] - m1n);
            float e3 = __expf(sc[nt][3] - m1n);
            ls0 += e0 + e1; ls1 += e2 + e3;
            uint2 u0; u0.x = f2tf(e0); u0.y = f2tf(e1);
            uint2 u1; u1.x = f2tf(e2); u1.y = f2tf(e3);
            int base0 = r0 * 128 + (((cl0 >> 2) ^ swz3(r0)) << 2) + (cl0 & 3);
            int base1 = r1 * 128 + (((cl0 >> 2) ^ swz3(r1)) << 2) + (cl0 & 3);
            *(uint2*)&Sp[base0] = u0;
            *(uint2*)&Sp[base1] = u1;
        }
        l0 = l0 * a0 + ls0;
        l1 = l1 * a1 + ls1;

#pragma unroll
        for (int nt = 0; nt < 2; nt++) {
            acco[nt][0] *= a0; acco[nt][1] *= a0;
            acco[nt][2] *= a1; acco[nt][3] *= a1;
        }
        bar_named(wm + 1);

#pragma unroll
        for (int kg8 = 0; kg8 < 32; kg8 += 2) {
            uint32_t af[4], bv[4];
            ldsmA<32>(af, baseKb[cur], wm * 16, kg8, lane);
            ldsmB<32>(bv, baseVb[cur], wn * 16, kg8, lane);
            mma_tf32(acco[0], af[0], af[1], af[2], af[3], bv[0], bv[1]);
            mma_tf32(acco[1], af[0], af[1], af[2], af[3], bv[2], bv[3]);
        }
    }

    // -------- peeled final tile (with causal skip guards) --------
    {
        int jt = ntiles - 1;
        int c0 = jt * 128;
        int R0 = (LS - 1) + c0 - i0;
        int cur = jt & 1;
        int cl_lim = i0 + 63 - c0;                         // 63 or 127
        int jjmax  = (cl_lim < 127 ? cl_lim : 127) + 63;
        int rlim   = i0 + wm * 16 + 15 - c0;
        __syncthreads();

#pragma unroll
        for (int it = 0; it < 6; it++) {
            int f = tid + it * 512, j = f >> 4, c4 = f & 15;
            int src = R0 - 63 + j;
            src = src < 0 ? 0 : (src > LS - 1 ? LS - 1 : src);
            cp16(baseQm + (uint32_t)((j * 16 + (c4 ^ swz3(j))) << 4),
                 &g_Qm[(size_t)src * DS + h * HDM + c4 * 4]);
        }
        asm volatile("cp.async.commit_group;" ::: "memory");

        if (tid < 192) {
            int idx = R0 - 63 + tid;
            dsl[tid] = (idx >= 0 && idx < LS) ? Db[idx] : 0.f;
        }
        if (tid >= 256 && tid < 384) {
            int t = tid - 256;
            cks[t] = ckb[c0 + t];
        }

        asm volatile("cp.async.wait_group 1;" ::: "memory");
        __syncthreads();

        float sc[4][4];
#pragma unroll
        for (int nt = 0; nt < 4; nt++)
#pragma unroll
            for (int e = 0; e < 4; e++) sc[nt][e] = 0.f;
        uint32_t aq[8][4];
#pragma unroll
        for (int kg8 = 0; kg8 < 16; kg8 += 2) {
            ldsmA<16>(aq[kg8 >> 1], baseQ, wm * 16, kg8, lane);
#pragma unroll
            for (int p = 0; p < 2; p++) {
                if (wn * 32 + p * 16 <= rlim) {
                    uint32_t bk[4];
                    ldsmB<16>(bk, baseKb[cur], wn * 32 + p * 16, kg8, lane);
                    mma_tf32(sc[2*p],   aq[kg8>>1][0], aq[kg8>>1][1], aq[kg8>>1][2], aq[kg8>>1][3], bk[0], bk[1]);
                    mma_tf32(sc[2*p+1], aq[kg8>>1][0], aq[kg8>>1][1], aq[kg8>>1][2], aq[kg8>>1][3], bk[2], bk[3]);
                }
            }
        }

        asm volatile("cp.async.wait_group 0;" ::: "memory");
        __syncthreads();

        float br[6][4];
#pragma unroll
        for (int nt = 0; nt < 6; nt++)
#pragma unroll
            for (int e = 0; e < 4; e++) br[nt][e] = 0.f;
#pragma unroll
        for (int kg8 = 0; kg8 < 16; kg8 += 2) {
#pragma unroll
            for (int p = 0; p < 3; p++) {
                int nb = wn * 48 + p * 16;
                if (nb <= jjmax) {
                    uint32_t bq[4];
                    ldsmB<16>(bq, baseQm, nb, kg8, lane);
                    mma_tf32(br[2*p],   aq[kg8>>1][0], aq[kg8>>1][1], aq[kg8>>1][2], aq[kg8>>1][3], bq[0], bq[1]);
                    mma_tf32(br[2*p+1], aq[kg8>>1][0], aq[kg8>>1][1], aq[kg8>>1][2], aq[kg8>>1][3], bq[2], bq[3]);
                }
            }
        }
        __syncthreads();

#pragma unroll
        for (int nt = 0; nt < 6; nt++) {
            int nb = wn * 48 + (nt >> 1) * 16;
            if (nb <= jjmax) {
                int col = wn * 48 + nt * 8 + tg * 2;
                float d0 = dsl[col], d1 = dsl[col + 1];
                *(float2*)&Brl[r0 * 200 + col] = make_float2(br[nt][0] + d0, br[nt][1] + d1);
                *(float2*)&Brl[r1 * 200 + col] = make_float2(br[nt][2] + d0, br[nt][3] + d1);
            }
        }
        bar_named(wm + 1);

#pragma unroll
        for (int nt = 0; nt < 4; nt++) {
            int cl0 = wn * 32 + nt * 8 + tg * 2;
#pragma unroll
            for (int e = 0; e < 4; e++) {
                int r  = (e >= 2) ? r1 : r0;
                int cl = cl0 + (e & 1);
                float v;
                if (c0 + cl > i0 + r) {
                    v = -INFINITY;
                } else {
                    float bd = Brl[r * 200 + (cl - r + 63)];
                    v = sc[nt][e] + cks[cl] + bd;
                    if (c0 + cl == i0 + r) v += bd;
                }
                sc[nt][e] = v;
            }
        }

        float mx0 = -INFINITY, mx1 = -INFINITY;
#pragma unroll
        for (int nt = 0; nt < 4; nt++) {
            mx0 = fmaxf(mx0, fmaxf(sc[nt][0], sc[nt][1]));
            mx1 = fmaxf(mx1, fmaxf(sc[nt][2], sc[nt][3]));
        }
        mx0 = fmaxf(mx0, __shfl_xor_sync(0xffffffffu, mx0, 1));
        mx0 = fmaxf(mx0, __shfl_xor_sync(0xffffffffu, mx0, 2));
        mx1 = fmaxf(mx1, __shfl_xor_sync(0xffffffffu, mx1, 1));
        mx1 = fmaxf(mx1, __shfl_xor_sync(0xffffffffu, mx1, 2));
        if (tg == 0) { mred[r0 * 4 + wn] = mx0; mred[r1 * 4 + wn] = mx1; }
        bar_named(wm + 1);
        float4 ma = *(const float4*)&mred[r0 * 4];
        float4 mb = *(const float4*)&mred[r1 * 4];
        float m0n = fmaxf(m0, fmaxf(fmaxf(ma.x, ma.y), fmaxf(ma.z, ma.w)));
        float m1n = fmaxf(m1, fmaxf(fmaxf(mb.x, mb.y), fmaxf(mb.z, mb.w)));
        float a0 = __expf(m0 - m0n), a1 = __expf(m1 - m1n);
        m0 = m0n; m1 = m1n;

        uint32_t* Sp = ksbuf[cur];
        float ls0 = 0.f, ls1 = 0.f;
#pragma unroll
        for (int nt = 0; nt < 4; nt++) {
            int cl0 = wn * 32 + nt * 8 + tg * 2;
            float e0 = __expf(sc[nt][0] - m0n);
            float e1 = __expf(sc[nt][1] - m0n);
            float e2 = __expf(sc[nt][2] - m1n);
            float e3 = __expf(sc[nt][3] - m1n);
            ls0 += e0 + e1; ls1 += e2 + e3;
            uint2 u0; u0.x = f2tf(e0); u0.y = f2tf(e1);
            uint2 u1; u1.x = f2tf(e2); u1.y = f2tf(e3);
            int base0 = r0 * 128 + (((cl0 >> 2) ^ swz3(r0)) << 2) + (cl0 & 3);
            int base1 = r1 * 128 + (((cl0 >> 2) ^ swz3(r1)) << 2) + (cl0 & 3);
            *(uint2*)&Sp[base0] = u0;
            *(uint2*)&Sp[base1] = u1;
        }
        l0 = l0 * a0 + ls0;
        l1 = l1 * a1 + ls1;

#pragma unroll
        for (int nt = 0; nt < 2; nt++) {
            acco[nt][0] *= a0; acco[nt][1] *= a0;
            acco[nt][2] *= a1; acco[nt][3] *= a1;
        }
        bar_named(wm + 1);

#pragma unroll
        for (int kg8 = 0; kg8 < 32; kg8 += 2) {
            if (kg8 * 4 <= cl_lim) {
                uint32_t af[4], bv[4];
                ldsmA<32>(af, baseKb[cur], wm * 16, kg8, lane);
                ldsmB<32>(bv, baseVb[cur], wn * 16, kg8, lane);
                mma_tf32(acco[0], af[0], af[1], af[2], af[3], bv[0], bv[1]);
                mma_tf32(acco[1], af[0], af[1], af[2], af[3], bv[2], bv[3]);
            }
        }
    }

    l0 += __shfl_xor_sync(0xffffffffu, l0, 1);
    l0 += __shfl_xor_sync(0xffffffffu, l0, 2);
    l1 += __shfl_xor_sync(0xffffffffu, l1, 1);
    l1 += __shfl_xor_sync(0xffffffffu, l1, 2);
    bar_named(wm + 1);
    if (tg == 0) { mred[r0 * 4 + wn] = l0; mred[r1 * 4 + wn] = l1; }
    bar_named(wm + 1);
    float4 la = *(const float4*)&mred[r0 * 4];
    float4 lb = *(const float4*)&mred[r1 * 4];
    float i1 = 1.f / (la.x + la.y + la.z + la.w);
    float i2 = 1.f / (lb.x + lb.y + lb.z + lb.w);
#pragma unroll
    for (int nt = 0; nt < 2; nt++) {
        int col = h * HDM + wn * 16 + nt * 8 + tg * 2;
        size_t w1 = (size_t)(n * LS + i0 + r0) * DS + col;
        size_t w2 = w1 + (size_t)8 * DS;
        *(float2*)&g_O[w1] = make_float2(rndtf(acco[nt][0] * i1), rndtf(acco[nt][1] * i1));
        *(float2*)&g_O[w2] = make_float2(rndtf(acco[nt][2] * i2), rndtf(acco[nt][3] * i2));
    }
}

// ---------------- row layernorm ---------------------------------------------
__global__ void k_ln(const float* __restrict__ g, const float* __restrict__ b,
                     float* __restrict__ out) {
    int row = blockIdx.x, tid = threadIdx.x;
    const float* z = g_Z + (size_t)row * DS;
    __shared__ float red[256];
    __shared__ float s_mu, s_rstd;
    float4 zv = *(const float4*)&z[tid * 4];
    float s = zv.x + zv.y + zv.z + zv.w;
    red[tid] = s; __syncthreads();
    for (int o = 128; o > 0; o >>= 1) { if (tid < o) red[tid] += red[tid + o]; __syncthreads(); }
    if (tid == 0) s_mu = red[0] * (1.f / DS);
    __syncthreads();
    float mu = s_mu;
    float dx = zv.x - mu, dy = zv.y - mu, dz = zv.z - mu, dw = zv.w - mu;
    red[tid] = dx*dx + dy*dy + dz*dz + dw*dw; __syncthreads();
    for (int o = 128; o > 0; o >>= 1) { if (tid < o) red[tid] += red[tid + o]; __syncthreads(); }
    if (tid == 0) s_rstd = rsqrtf(red[0] * (1.f / DS) + 1e-5f);
    __syncthreads();
    float rstd = s_rstd;
    float4 gv = *(const float4*)&g[tid * 4];
    float4 bv = *(const float4*)&b[tid * 4];
    float4 ov;
    ov.x = dx * rstd * gv.x + bv.x;
    ov.y = dy * rstd * gv.y + bv.y;
    ov.z = dz * rstd * gv.z + bv.z;
    ov.w = dw * rstd * gv.w + bv.w;
    *(float4*)&out[(size_t)row * DS + tid * 4] = ov;
}

// ---------------- launch ------------------------------------------------------
extern "C" void kernel_launch(void* const* d_in, const int* in_sizes, int n_in,
                              void* d_out, int out_size) {
    const float* X   = (const float*)d_in[0];
    const float* Y   = (const float*)d_in[1];
    const float* Wq  = (const float*)d_in[4];
    const float* We  = (const float*)d_in[5];
    const float* Wv  = (const float*)d_in[6];
    const float* Wr  = (const float*)d_in[7];
    const float* cb  = (const float*)d_in[8];
    const float* pb  = (const float*)d_in[9];
    const float* Wo  = (const float*)d_in[10];
    const float* Wob = (const float*)d_in[11];
    const float* lng = (const float*)d_in[12];
    const float* lnb = (const float*)d_in[13];
    float* out = (float*)d_out;

    float *Op, *Zp, *WoRp;
    cudaGetSymbolAddress((void**)&Op, g_O);
    cudaGetSymbolAddress((void**)&Zp, g_Z);
    cudaGetSymbolAddress((void**)&WoRp, g_WoR);

    cudaFuncSetAttribute(k_flash, cudaFuncAttributeMaxDynamicSharedMemorySize,
                         FL_SMEM_FLOATS * (int)sizeof(float));
    cudaFuncSetAttribute(k_mma<1>, cudaFuncAttributeMaxDynamicSharedMemorySize,
                         GEMM_SMEM_BYTES);
    cudaFuncSetAttribute(k_mma_proj, cudaFuncAttributeMaxDynamicSharedMemorySize,
                         GEMM_SMEM_BYTES);

    // merged prep: rope + weight transposes + rounded copies
    int prep_blocks = 2048 + 4096 + (2 * (NLR * DS / 4) + DS * DS / 4 + 255) / 256;
    k_prep<<<prep_blocks, 256>>>(X, Y, Wq, We, Wv, Wr, Wo);

    // fused projections: q/k/vT (z=0..2) + Qm = R@Wr (z=3)
    k_mma_proj<<<dim3(DS/128, NLR/128, 4), 256, GEMM_SMEM_BYTES>>>();

    // ck + Dv tables
    k_tabs<<<(NB * NHD * LS + NHD * LS) / 16, 256>>>(cb, pb);

    // fused causal attention (64x128 tiles, peeled final tile with skips)
    k_flash<<<dim3(LS / 64, NB * NHD), 512, FL_SMEM_FLOATS * sizeof(float)>>>();

    // Z = X + O @ Wo^T + Wo_b
    k_mma<1><<<dim3(DS/128, NLR/128), 256, GEMM_SMEM_BYTES>>>(
        Op, DS, WoRp, DS, Zp, DS, DS, Wob, X);

    // layernorm -> out
    k_ln<<<NLR, 256>>>(lng, lnb, out);
}